// round 1
// baseline (speedup 1.0000x reference)
#include <cuda_runtime.h>

#define TPB      128
#define ROWS_PB  128

__device__ __forceinline__ void fma2(unsigned long long &d,
                                     unsigned long long a,
                                     unsigned long long b) {
    asm("fma.rn.f32x2 %0, %1, %2, %0;" : "+l"(d) : "l"(a), "l"(b));
}

__device__ __forceinline__ unsigned long long pack2(float x, float y) {
    unsigned long long r;
    asm("mov.b64 %0, {%1, %2};" : "=l"(r) : "f"(x), "f"(y));
    return r;
}

__device__ __forceinline__ float2 unpack2(unsigned long long v) {
    float2 r;
    asm("mov.b64 {%0, %1}, %2;" : "=f"(r.x), "=f"(r.y) : "l"(v));
    return r;
}

__global__ void __launch_bounds__(TPB, 4) fused_gemm_scatter(
    const float* __restrict__ x,
    const float* __restrict__ w,
    const float* __restrict__ bias,
    const int*   __restrict__ idx,
    float*       __restrict__ out,
    int n_rows)
{
    // Ws[k][o] = w[o][k]  (transposed so 8 consecutive o's are one LDS128)
    __shared__ float Ws[64][64];
    // Xs[r][k ^ ((r&3)<<2)] = x[r][k]  (swizzle kills 4-way bank conflicts
    // on the strided per-thread scalar x loads in the mainloop)
    __shared__ float Xs[ROWS_PB][64];

    const int tid = threadIdx.x;
    const long long row0 = (long long)blockIdx.x * ROWS_PB;

    // ---- stage W transposed (one-time, 16 KB) ----
    #pragma unroll
    for (int t = tid; t < 64 * 64; t += TPB) {
        int o = t >> 6, k = t & 63;
        Ws[k][o] = w[t];
    }

    // ---- stage X: coalesced float4 global loads, swizzled STS128 ----
    {
        const int kc = tid & 15;   // float4 chunk within row (0..15)
        const int rb = tid >> 4;   // row sub-index (0..7)
        #pragma unroll
        for (int p = 0; p < 16; p++) {
            int r = p * 8 + rb;
            long long grow = row0 + r;
            float4 v = make_float4(0.f, 0.f, 0.f, 0.f);
            if (grow < n_rows)
                v = *(const float4*)(x + grow * 64 + kc * 4);
            int kcs = kc ^ (r & 3);                 // swizzle bits 2..3 of k
            *(float4*)&Xs[r][kcs * 4] = v;
        }
    }
    __syncthreads();

    const int tc = tid & 7;     // output-channel group: o in [tc*8, tc*8+8)
    const int tr = tid >> 3;    // row group: rows tr + 16*m, m = 0..7
    const int sw = (tr & 3) << 2;

    // 8 rows x 8 outs per thread, accumulated as f32x2 pairs along o
    unsigned long long acc[8][4];
    #pragma unroll
    for (int m = 0; m < 8; m++)
        #pragma unroll
        for (int j = 0; j < 4; j++)
            acc[m][j] = 0ull;

    #pragma unroll 4
    for (int k = 0; k < 64; k++) {
        const float4 w0 = *(const float4*)&Ws[k][tc * 8];
        const float4 w1 = *(const float4*)&Ws[k][tc * 8 + 4];
        unsigned long long wp[4];
        wp[0] = pack2(w0.x, w0.y);
        wp[1] = pack2(w0.z, w0.w);
        wp[2] = pack2(w1.x, w1.y);
        wp[3] = pack2(w1.z, w1.w);

        #pragma unroll
        for (int m = 0; m < 8; m++) {
            float xv = Xs[tr + 16 * m][k ^ sw];
            unsigned long long xx = pack2(xv, xv);
            #pragma unroll
            for (int j = 0; j < 4; j++)
                fma2(acc[m][j], xx, wp[j]);
        }
    }

    // ---- epilogue: + bias, scatter via vector reductions ----
    unsigned long long bp[4];
    {
        const float4 b0 = *(const float4*)(bias + tc * 8);
        const float4 b1 = *(const float4*)(bias + tc * 8 + 4);
        bp[0] = pack2(b0.x, b0.y);
        bp[1] = pack2(b0.z, b0.w);
        bp[2] = pack2(b1.x, b1.y);
        bp[3] = pack2(b1.z, b1.w);
    }

    #pragma unroll
    for (int m = 0; m < 8; m++) {
        long long grow = row0 + tr + 16 * m;
        if (grow < n_rows) {
            int seg = idx[grow];
            float* dst = out + (size_t)seg * 64 + tc * 8;

            float2 f[4];
            #pragma unroll
            for (int j = 0; j < 4; j++) {
                unsigned long long s;
                asm("add.rn.f32x2 %0, %1, %2;" : "=l"(s) : "l"(acc[m][j]), "l"(bp[j]));
                f[j] = unpack2(s);
            }
            asm volatile("red.global.add.v4.f32 [%0], {%1, %2, %3, %4};"
                         :: "l"(dst),     "f"(f[0].x), "f"(f[0].y),
                            "f"(f[1].x), "f"(f[1].y) : "memory");
            asm volatile("red.global.add.v4.f32 [%0], {%1, %2, %3, %4};"
                         :: "l"(dst + 4), "f"(f[2].x), "f"(f[2].y),
                            "f"(f[3].x), "f"(f[3].y) : "memory");
        }
    }
}

extern "C" void kernel_launch(void* const* d_in, const int* in_sizes, int n_in,
                              void* d_out, int out_size) {
    const float* x    = (const float*)d_in[0];
    const float* w    = (const float*)d_in[1];
    const float* bias = (const float*)d_in[2];
    const int*   idx  = (const int*)d_in[3];
    float*       out  = (float*)d_out;

    const int n_rows = in_sizes[0] / 64;

    // out is poisoned to 0xAA by the harness; zero it (memset node in graph)
    cudaMemsetAsync(d_out, 0, (size_t)out_size * sizeof(float), 0);

    int blocks = (n_rows + ROWS_PB - 1) / ROWS_PB;
    fused_gemm_scatter<<<blocks, TPB>>>(x, w, bias, idx, out, n_rows);
}

// round 3
// speedup vs baseline: 2.5181x; 2.5181x over previous
#include <cuda_runtime.h>
#include <cstdint>

#define TPB      128
#define ROWS_PB  128

// ---- dynamic smem layout ----
#define SM_BIAS   0                        // 64 f32 = 256B
#define SM_A_HI   1024                     // 128 x 64 bf16, SW128 = 16KB
#define SM_A_LO   (1024 + 16384)           // 16KB
#define SM_B_HI   (1024 + 32768)           // 64 x 64 bf16, SW128 = 8KB
#define SM_B_LO   (1024 + 32768 + 8192)    // 8KB
#define SM_T      1024                     // transpose region (reuses A/B, post-sync)
#define T_STRIDE  272                      // 256B row + 16B pad (bank rotate)
#define SMEM_BYTES (1024 + 32768 + 16384)  // 50176 (T needs 128*272=34816 <= 49152)

// SW128 swizzle on byte offset within a 128B-row tile
#define SW128(o) ((o) ^ (((o) >> 3) & 0x70))

__device__ __forceinline__ uint32_t smem_u32(const void* p) {
    uint32_t a;
    asm("{ .reg .u64 t; cvta.to.shared.u64 t, %1; cvt.u32.u64 %0, t; }" : "=r"(a) : "l"(p));
    return a;
}

// pack two f32 -> bf16x2 (memory order [a, b]), round-to-nearest
__device__ __forceinline__ uint32_t cvt_bf16x2(float a, float b) {
    uint32_t r;
    asm("cvt.rn.bf16x2.f32 %0, %1, %2;" : "=r"(r) : "f"(b), "f"(a));
    return r;
}

__device__ __forceinline__ void split4(float4 v, uint32_t& h0, uint32_t& h1,
                                       uint32_t& l0, uint32_t& l1) {
    h0 = cvt_bf16x2(v.x, v.y);
    h1 = cvt_bf16x2(v.z, v.w);
    float rx = v.x - __uint_as_float(h0 << 16);
    float ry = v.y - __uint_as_float(h0 & 0xFFFF0000u);
    float rz = v.z - __uint_as_float(h1 << 16);
    float rw = v.w - __uint_as_float(h1 & 0xFFFF0000u);
    l0 = cvt_bf16x2(rx, ry);
    l1 = cvt_bf16x2(rz, rw);
}

__device__ __forceinline__ void ldsm4(uint32_t* r, uint32_t addr) {
    asm volatile("ldmatrix.sync.aligned.m8n8.x4.shared.b16 {%0,%1,%2,%3}, [%4];"
                 : "=r"(r[0]), "=r"(r[1]), "=r"(r[2]), "=r"(r[3]) : "r"(addr));
}

__device__ __forceinline__ void mma_bf16(float* c, const uint32_t* a,
                                         uint32_t b0, uint32_t b1) {
    asm volatile(
        "mma.sync.aligned.m16n8k16.row.col.f32.bf16.bf16.f32 "
        "{%0,%1,%2,%3}, {%4,%5,%6,%7}, {%8,%9}, {%0,%1,%2,%3};"
        : "+f"(c[0]), "+f"(c[1]), "+f"(c[2]), "+f"(c[3])
        : "r"(a[0]), "r"(a[1]), "r"(a[2]), "r"(a[3]), "r"(b0), "r"(b1));
}

__global__ void __launch_bounds__(TPB, 4)
fused_mma_scatter(const float* __restrict__ x,
                  const float* __restrict__ w,
                  const float* __restrict__ bias,
                  const int*   __restrict__ idx,
                  float*       __restrict__ out,
                  int n_rows)
{
    extern __shared__ char smem[];
    const uint32_t sbase = smem_u32(smem);
    const int tid  = threadIdx.x;
    const int wid  = tid >> 5;
    const int lane = tid & 31;
    const long long row0 = (long long)blockIdx.x * ROWS_PB;

    // ---- stage W (64x64 f32 -> bf16 hi/lo, SW128) ----
    {
        const float4* w4 = (const float4*)w;
        #pragma unroll
        for (int i = tid; i < 1024; i += TPB) {
            float4 v = w4[i];
            int o = i >> 4, c = i & 15;
            uint32_t h0, h1, l0, l1;
            split4(v, h0, h1, l0, l1);
            uint32_t off = SW128((uint32_t)(o * 128 + c * 8));
            *(uint2*)(smem + SM_B_HI + off) = make_uint2(h0, h1);
            *(uint2*)(smem + SM_B_LO + off) = make_uint2(l0, l1);
        }
    }
    if (tid < 16) {
        float4 b4 = ((const float4*)bias)[tid];
        *(float4*)(smem + SM_BIAS + tid * 16) = b4;
    }
    // ---- stage X tile (128 rows x 64 f32 -> bf16 hi/lo, SW128) ----
    {
        #pragma unroll
        for (int it = 0; it < 16; it++) {
            int i = it * TPB + tid;
            int r = i >> 4, c = i & 15;
            long long grow = row0 + r;
            float4 v = make_float4(0.f, 0.f, 0.f, 0.f);
            if (grow < n_rows)
                v = *(const float4*)(x + grow * 64 + c * 4);
            uint32_t h0, h1, l0, l1;
            split4(v, h0, h1, l0, l1);
            uint32_t off = SW128((uint32_t)(r * 128 + c * 8));
            *(uint2*)(smem + SM_A_HI + off) = make_uint2(h0, h1);
            *(uint2*)(smem + SM_A_LO + off) = make_uint2(l0, l1);
        }
    }
    __syncthreads();

    // ---- ldmatrix lane addressing ----
    // A (m16k16, x4): lanes 0-7 rows0-7/k0 | 8-15 rows8-15/k0 | 16-23 rows0-7/k16B | 24-31 rows8-15/k16B
    const int rA  = (lane & 7) | (((lane >> 3) & 1) << 3);   // 0..15
    const int kbA = ((lane >> 4) & 1) * 16;
    // B (n8k16 pairs, x4): lanes 0-7 n0-7/k0 | 8-15 n0-7/k16B | 16-23 n8-15/k0 | 24-31 n8-15/k16B
    const int rB  = (lane & 7) | (((lane >> 4) & 1) << 3);
    const int kbB = ((lane >> 3) & 1) * 16;

    const uint32_t swA = (uint32_t)((rA & 7) << 4);
    const uint32_t swB = (uint32_t)((rB & 7) << 4);

    uint32_t aBase[2], bBase;
    #pragma unroll
    for (int mt = 0; mt < 2; mt++)
        aBase[mt] = sbase + SM_A_HI + (uint32_t)((wid * 32 + mt * 16 + rA) * 128);
    bBase = sbase + SM_B_HI + (uint32_t)(rB * 128);

    float acc[2][8][4];
    #pragma unroll
    for (int mt = 0; mt < 2; mt++)
        #pragma unroll
        for (int nt = 0; nt < 8; nt++)
            #pragma unroll
            for (int q = 0; q < 4; q++) acc[mt][nt][q] = 0.f;

    #pragma unroll
    for (int kt = 0; kt < 4; kt++) {
        const uint32_t kOffA = (uint32_t)(kt * 32 + kbA) ^ swA;
        const uint32_t kOffB = (uint32_t)(kt * 32 + kbB) ^ swB;

        uint32_t ah[2][4], al[2][4];
        #pragma unroll
        for (int mt = 0; mt < 2; mt++) {
            ldsm4(ah[mt], aBase[mt] + kOffA);
            ldsm4(al[mt], aBase[mt] + 16384u + kOffA);
        }

        #pragma unroll
        for (int jp = 0; jp < 4; jp++) {
            uint32_t bh[4], bl[4];
            uint32_t baddr = bBase + (uint32_t)(jp * 2048) + kOffB;
            ldsm4(bh, baddr);
            ldsm4(bl, baddr + 8192u);

            #pragma unroll
            for (int mt = 0; mt < 2; mt++) {
                mma_bf16(acc[mt][2 * jp + 0], ah[mt], bh[0], bh[1]);
                mma_bf16(acc[mt][2 * jp + 0], al[mt], bh[0], bh[1]);
                mma_bf16(acc[mt][2 * jp + 0], ah[mt], bl[0], bl[1]);
                mma_bf16(acc[mt][2 * jp + 1], ah[mt], bh[2], bh[3]);
                mma_bf16(acc[mt][2 * jp + 1], al[mt], bh[2], bh[3]);
                mma_bf16(acc[mt][2 * jp + 1], ah[mt], bl[2], bl[3]);
            }
        }
    }
    __syncthreads();    // everyone done with A/B smem (region reused below)

    // ---- bias regs for this lane's columns ----
    float bj[16];
    {
        const float* biasS = (const float*)(smem + SM_BIAS);
        const int cb = (lane & 3) * 2;
        #pragma unroll
        for (int nt = 0; nt < 8; nt++) {
            float2 b2 = *(const float2*)(biasS + nt * 8 + cb);
            bj[2 * nt]     = b2.x;
            bj[2 * nt + 1] = b2.y;
        }
    }

    // ---- transpose accs (+bias) into linear rows for bulk-reduce ----
    // acc (mt, nt): c0,c1 row = wid*32+mt*16+lane/4 ; c2,c3 row +8 ; cols nt*8+(lane&3)*2
    {
        #pragma unroll
        for (int mt = 0; mt < 2; mt++)
            #pragma unroll
            for (int h = 0; h < 2; h++) {
                int r = wid * 32 + mt * 16 + (lane >> 2) + 8 * h;
                char* rowp = smem + SM_T + r * T_STRIDE + (lane & 3) * 8;
                #pragma unroll
                for (int nt = 0; nt < 8; nt++) {
                    float2 v;
                    v.x = acc[mt][nt][2 * h]     + bj[2 * nt];
                    v.y = acc[mt][nt][2 * h + 1] + bj[2 * nt + 1];
                    *(float2*)(rowp + nt * 32) = v;
                }
            }
    }
    asm volatile("fence.proxy.async.shared::cta;" ::: "memory");
    __syncthreads();

    // ---- scatter: one bulk reduce-add (256B) per row via TMA engine ----
    {
        long long grow = row0 + tid;
        if (grow < n_rows) {
            int seg = idx[grow];
            float* dst = out + (size_t)seg * 64;
            uint32_t src = sbase + SM_T + (uint32_t)(tid * T_STRIDE);
            asm volatile(
                "cp.reduce.async.bulk.global.shared::cta.bulk_group.add.f32 "
                "[%0], [%1], %2;"
                :: "l"(dst), "r"(src), "r"(256) : "memory");
        }
        asm volatile("cp.async.bulk.commit_group;" ::: "memory");
        asm volatile("cp.async.bulk.wait_group 0;" ::: "memory");
    }
}

extern "C" void kernel_launch(void* const* d_in, const int* in_sizes, int n_in,
                              void* d_out, int out_size) {
    const float* x    = (const float*)d_in[0];
    const float* w    = (const float*)d_in[1];
    const float* bias = (const float*)d_in[2];
    const int*   idx  = (const int*)d_in[3];
    float*       out  = (float*)d_out;

    const int n_rows = in_sizes[0] / 64;

    cudaFuncSetAttribute(fused_mma_scatter,
                         cudaFuncAttributeMaxDynamicSharedMemorySize, SMEM_BYTES);

    cudaMemsetAsync(d_out, 0, (size_t)out_size * sizeof(float), 0);

    int blocks = (n_rows + ROWS_PB - 1) / ROWS_PB;
    fused_mma_scatter<<<blocks, TPB, SMEM_BYTES>>>(x, w, bias, idx, out, n_rows);
}

// round 4
// speedup vs baseline: 3.1738x; 1.2604x over previous
#include <cuda_runtime.h>
#include <cstdint>

#define TPB      256
#define ROWS_PB  128

// ---- dynamic smem layout ----
#define SM_BIAS   0                        // 64 f32 = 256B
#define SM_A_HI   1024                     // 128 x 64 bf16, SW128 = 16KB
#define SM_A_LO   (1024 + 16384)           // 16KB
#define SM_B_HI   (1024 + 32768)           // 64 x 64 bf16, SW128 = 8KB
#define SM_B_LO   (1024 + 32768 + 8192)    // 8KB
#define SM_T      1024                     // transpose region (reuses A/B, post-sync)
#define T_STRIDE  272                      // 256B row + 16B pad (bank rotate)
#define SMEM_BYTES (1024 + 32768 + 16384)  // 50176

// SW128 swizzle on byte offset within a 128B-row tile
#define SW128(o) ((o) ^ (((o) >> 3) & 0x70))

__device__ __forceinline__ uint32_t smem_u32(const void* p) {
    uint32_t a;
    asm("{ .reg .u64 t; cvta.to.shared.u64 t, %1; cvt.u32.u64 %0, t; }" : "=r"(a) : "l"(p));
    return a;
}

__device__ __forceinline__ uint32_t cvt_bf16x2(float a, float b) {
    uint32_t r;
    asm("cvt.rn.bf16x2.f32 %0, %1, %2;" : "=r"(r) : "f"(b), "f"(a));
    return r;
}

__device__ __forceinline__ void split4(float4 v, uint32_t& h0, uint32_t& h1,
                                       uint32_t& l0, uint32_t& l1) {
    h0 = cvt_bf16x2(v.x, v.y);
    h1 = cvt_bf16x2(v.z, v.w);
    float rx = v.x - __uint_as_float(h0 << 16);
    float ry = v.y - __uint_as_float(h0 & 0xFFFF0000u);
    float rz = v.z - __uint_as_float(h1 << 16);
    float rw = v.w - __uint_as_float(h1 & 0xFFFF0000u);
    l0 = cvt_bf16x2(rx, ry);
    l1 = cvt_bf16x2(rz, rw);
}

__device__ __forceinline__ void ldsm4(uint32_t* r, uint32_t addr) {
    asm volatile("ldmatrix.sync.aligned.m8n8.x4.shared.b16 {%0,%1,%2,%3}, [%4];"
                 : "=r"(r[0]), "=r"(r[1]), "=r"(r[2]), "=r"(r[3]) : "r"(addr));
}

__device__ __forceinline__ void mma_bf16(float* c, const uint32_t* a,
                                         uint32_t b0, uint32_t b1) {
    asm volatile(
        "mma.sync.aligned.m16n8k16.row.col.f32.bf16.bf16.f32 "
        "{%0,%1,%2,%3}, {%4,%5,%6,%7}, {%8,%9}, {%0,%1,%2,%3};"
        : "+f"(c[0]), "+f"(c[1]), "+f"(c[2]), "+f"(c[3])
        : "r"(a[0]), "r"(a[1]), "r"(a[2]), "r"(a[3]), "r"(b0), "r"(b1));
}

__global__ void __launch_bounds__(TPB, 3)
fused_mma_scatter(const float* __restrict__ x,
                  const float* __restrict__ w,
                  const float* __restrict__ bias,
                  const int*   __restrict__ idx,
                  float*       __restrict__ out,
                  int n_rows)
{
    extern __shared__ char smem[];
    const uint32_t sbase = smem_u32(smem);
    const int tid  = threadIdx.x;
    const int wid  = tid >> 5;
    const int lane = tid & 31;
    const int wg_row = wid & 3;     // 4 row-groups of 32 rows
    const int wg_col = wid >> 2;    // 2 col-groups of 32 cols
    const long long row0 = (long long)blockIdx.x * ROWS_PB;

    // ---- stage W (64x64 f32 -> bf16 hi/lo, SW128) ----
    {
        const float4* w4 = (const float4*)w;
        #pragma unroll
        for (int it = 0; it < 4; it++) {
            int i = it * TPB + tid;              // 0..1023
            float4 v = w4[i];
            int o = i >> 4, c = i & 15;
            uint32_t h0, h1, l0, l1;
            split4(v, h0, h1, l0, l1);
            uint32_t off = SW128((uint32_t)(o * 128 + c * 8));
            *(uint2*)(smem + SM_B_HI + off) = make_uint2(h0, h1);
            *(uint2*)(smem + SM_B_LO + off) = make_uint2(l0, l1);
        }
    }
    if (tid < 16) {
        float4 b4 = ((const float4*)bias)[tid];
        *(float4*)(smem + SM_BIAS + tid * 16) = b4;
    }
    // ---- stage X tile (128 rows x 64 f32 -> bf16 hi/lo, SW128) ----
    {
        #pragma unroll
        for (int it = 0; it < 8; it++) {
            int i = it * TPB + tid;              // 0..2047 float4s
            int r = i >> 4, c = i & 15;
            long long grow = row0 + r;
            float4 v = make_float4(0.f, 0.f, 0.f, 0.f);
            if (grow < n_rows)
                v = *(const float4*)(x + grow * 64 + c * 4);
            uint32_t h0, h1, l0, l1;
            split4(v, h0, h1, l0, l1);
            uint32_t off = SW128((uint32_t)(r * 128 + c * 8));
            *(uint2*)(smem + SM_A_HI + off) = make_uint2(h0, h1);
            *(uint2*)(smem + SM_A_LO + off) = make_uint2(l0, l1);
        }
    }
    __syncthreads();

    // ---- ldmatrix lane addressing ----
    const int rA  = (lane & 7) | (((lane >> 3) & 1) << 3);   // 0..15
    const int kbA = ((lane >> 4) & 1) * 16;
    const int rB  = (lane & 7) | (((lane >> 4) & 1) << 3);
    const int kbB = ((lane >> 3) & 1) * 16;

    const uint32_t swA = (uint32_t)((rA & 7) << 4);
    const uint32_t swB = (uint32_t)((rB & 7) << 4);

    uint32_t aBase[2];
    #pragma unroll
    for (int mt = 0; mt < 2; mt++)
        aBase[mt] = sbase + SM_A_HI +
                    (uint32_t)((wg_row * 32 + mt * 16 + rA) * 128);
    const uint32_t bBase = sbase + SM_B_HI +
                           (uint32_t)(wg_col * 4096 + rB * 128);

    // 32 rows x 32 cols per warp: acc[mt][nt][q], nt = 8-col tile in col-group
    float acc[2][4][4];
    #pragma unroll
    for (int mt = 0; mt < 2; mt++)
        #pragma unroll
        for (int nt = 0; nt < 4; nt++)
            #pragma unroll
            for (int q = 0; q < 4; q++) acc[mt][nt][q] = 0.f;

    #pragma unroll
    for (int kt = 0; kt < 4; kt++) {
        const uint32_t kOffA = (uint32_t)(kt * 32 + kbA) ^ swA;
        const uint32_t kOffB = (uint32_t)(kt * 32 + kbB) ^ swB;

        uint32_t ah[2][4], al[2][4];
        #pragma unroll
        for (int mt = 0; mt < 2; mt++) {
            ldsm4(ah[mt], aBase[mt] + kOffA);
            ldsm4(al[mt], aBase[mt] + 16384u + kOffA);
        }

        #pragma unroll
        for (int jp = 0; jp < 2; jp++) {
            uint32_t bh[4], bl[4];
            uint32_t baddr = bBase + (uint32_t)(jp * 2048) + kOffB;
            ldsm4(bh, baddr);
            ldsm4(bl, baddr + 8192u);

            #pragma unroll
            for (int mt = 0; mt < 2; mt++) {
                mma_bf16(acc[mt][2 * jp + 0], ah[mt], bh[0], bh[1]);
                mma_bf16(acc[mt][2 * jp + 0], al[mt], bh[0], bh[1]);
                mma_bf16(acc[mt][2 * jp + 0], ah[mt], bl[0], bl[1]);
                mma_bf16(acc[mt][2 * jp + 1], ah[mt], bh[2], bh[3]);
                mma_bf16(acc[mt][2 * jp + 1], al[mt], bh[2], bh[3]);
                mma_bf16(acc[mt][2 * jp + 1], ah[mt], bl[2], bl[3]);
            }
        }
    }
    __syncthreads();    // everyone done with A/B smem (region reused below)

    // ---- bias regs for this lane's columns ----
    float bj[8];
    {
        const float* biasS = (const float*)(smem + SM_BIAS);
        const int cb = wg_col * 32 + (lane & 3) * 2;
        #pragma unroll
        for (int nt = 0; nt < 4; nt++) {
            float2 b2 = *(const float2*)(biasS + cb + nt * 8);
            bj[2 * nt]     = b2.x;
            bj[2 * nt + 1] = b2.y;
        }
    }

    // ---- transpose accs (+bias) into linear rows for bulk-reduce ----
    {
        #pragma unroll
        for (int mt = 0; mt < 2; mt++)
            #pragma unroll
            for (int h = 0; h < 2; h++) {
                int r = wg_row * 32 + mt * 16 + (lane >> 2) + 8 * h;
                char* rowp = smem + SM_T + r * T_STRIDE +
                             wg_col * 128 + (lane & 3) * 8;
                #pragma unroll
                for (int nt = 0; nt < 4; nt++) {
                    float2 v;
                    v.x = acc[mt][nt][2 * h]     + bj[2 * nt];
                    v.y = acc[mt][nt][2 * h + 1] + bj[2 * nt + 1];
                    *(float2*)(rowp + nt * 32) = v;
                }
            }
    }
    asm volatile("fence.proxy.async.shared::cta;" ::: "memory");
    __syncthreads();

    // ---- scatter: one bulk reduce-add (256B) per row via TMA engine ----
    {
        long long grow = row0 + tid;
        if (tid < ROWS_PB && grow < n_rows) {
            int seg = idx[grow];
            float* dst = out + (size_t)seg * 64;
            uint32_t src = sbase + SM_T + (uint32_t)(tid * T_STRIDE);
            asm volatile(
                "cp.reduce.async.bulk.global.shared::cta.bulk_group.add.f32 "
                "[%0], [%1], %2;"
                :: "l"(dst), "r"(src), "r"(256) : "memory");
        }
        asm volatile("cp.async.bulk.commit_group;" ::: "memory");
        asm volatile("cp.async.bulk.wait_group 0;" ::: "memory");
    }
}

extern "C" void kernel_launch(void* const* d_in, const int* in_sizes, int n_in,
                              void* d_out, int out_size) {
    const float* x    = (const float*)d_in[0];
    const float* w    = (const float*)d_in[1];
    const float* bias = (const float*)d_in[2];
    const int*   idx  = (const int*)d_in[3];
    float*       out  = (float*)d_out;

    const int n_rows = in_sizes[0] / 64;

    cudaFuncSetAttribute(fused_mma_scatter,
                         cudaFuncAttributeMaxDynamicSharedMemorySize, SMEM_BYTES);

    cudaMemsetAsync(d_out, 0, (size_t)out_size * sizeof(float), 0);

    int blocks = (n_rows + ROWS_PB - 1) / ROWS_PB;
    fused_mma_scatter<<<blocks, TPB, SMEM_BYTES>>>(x, w, bias, idx, out, n_rows);
}